// round 1
// baseline (speedup 1.0000x reference)
#include <cuda_runtime.h>

// Problem constants
#define BB 4
#define LL 4096
#define DD 768
#define CHUNKS 128
#define ROWS (LL / CHUNKS)   // 32 rows per chunk

// Scratch (device globals — no allocation allowed in kernel_launch)
__device__ float g_probs[BB][LL];               // softmax of mask
__device__ float g_partial[CHUNKS][BB][DD];     // per-chunk weighted partial sums
__device__ float g_hbar[BB][DD];                // Σ_l probs·hs
__device__ float g_ctx[BB][DD];                 // hbar @ Wv^T + bv

// ---------------------------------------------------------------------------
// 1) probs[b,:] = softmax(mask[b,0,0,:])   — one block per batch
// ---------------------------------------------------------------------------
__global__ void probs_kernel(const float* __restrict__ mask) {
    const int b = blockIdx.x;
    const int t = threadIdx.x;                  // 1024 threads, 4 elems each
    const float* m = mask + (size_t)b * LL;

    __shared__ float red[1024];

    float v[4];
    float lmax = -3.0e38f;
    #pragma unroll
    for (int i = 0; i < 4; i++) {
        v[i] = m[t + i * 1024];
        lmax = fmaxf(lmax, v[i]);
    }
    red[t] = lmax;
    __syncthreads();
    for (int s = 512; s > 0; s >>= 1) {
        if (t < s) red[t] = fmaxf(red[t], red[t + s]);
        __syncthreads();
    }
    const float mx = red[0];
    __syncthreads();

    float e[4];
    float lsum = 0.0f;
    #pragma unroll
    for (int i = 0; i < 4; i++) {
        e[i] = expf(v[i] - mx);
        lsum += e[i];
    }
    red[t] = lsum;
    __syncthreads();
    for (int s = 512; s > 0; s >>= 1) {
        if (t < s) red[t] += red[t + s];
        __syncthreads();
    }
    const float inv = 1.0f / red[0];
    #pragma unroll
    for (int i = 0; i < 4; i++) g_probs[b][t + i * 1024] = e[i] * inv;
}

// ---------------------------------------------------------------------------
// 2) partial[c][b][d] = Σ_{l in chunk c} probs[b,l] * hs[b,l,d]
//    grid (CHUNKS, BB), 192 threads, float4 coalesced. 50 MB read — the
//    dominant read kernel; must stream at HBM bandwidth.
// ---------------------------------------------------------------------------
__global__ void wsum_kernel(const float* __restrict__ hs) {
    const int c = blockIdx.x;
    const int b = blockIdx.y;
    const int t = threadIdx.x;                  // 192 = DD/4

    __shared__ float p[ROWS];
    if (t < ROWS) p[t] = g_probs[b][c * ROWS + t];
    __syncthreads();

    const float4* __restrict__ src =
        (const float4*)(hs + ((size_t)b * LL + (size_t)c * ROWS) * DD);

    float4 acc = make_float4(0.f, 0.f, 0.f, 0.f);
    #pragma unroll 8
    for (int r = 0; r < ROWS; r++) {
        const float4 x = src[(size_t)r * (DD / 4) + t];
        const float pr = p[r];
        acc.x = fmaf(pr, x.x, acc.x);
        acc.y = fmaf(pr, x.y, acc.y);
        acc.z = fmaf(pr, x.z, acc.z);
        acc.w = fmaf(pr, x.w, acc.w);
    }
    ((float4*)g_partial[c][b])[t] = acc;
}

// ---------------------------------------------------------------------------
// 3) hbar[b][d] = Σ_c partial[c][b][d]      (3072 outputs, 128 adds each)
// ---------------------------------------------------------------------------
__global__ void reduce_kernel() {
    const int idx = blockIdx.x * blockDim.x + threadIdx.x;  // 0..3071
    if (idx >= BB * DD) return;
    const int b = idx / DD;
    const int d = idx % DD;
    float s = 0.0f;
    #pragma unroll 8
    for (int c = 0; c < CHUNKS; c++) s += g_partial[c][b][d];
    g_hbar[b][d] = s;
}

// ---------------------------------------------------------------------------
// 4) ctx[b][d] = hbar[b,:] · Wv[d,:] + bv[d]   — one warp per output.
//    Wv rows read coalesced; Wv (2.3 MB) is L2-resident after first touch.
// ---------------------------------------------------------------------------
__global__ void gemv_kernel(const float* __restrict__ Wv,
                            const float* __restrict__ bv) {
    const int warp = (blockIdx.x * blockDim.x + threadIdx.x) >> 5;  // 0..3071
    const int lane = threadIdx.x & 31;
    if (warp >= BB * DD) return;
    const int b = warp / DD;
    const int d = warp % DD;

    const float4* __restrict__ h = (const float4*)g_hbar[b];
    const float4* __restrict__ w = (const float4*)(Wv + (size_t)d * DD);

    float s = 0.0f;
    #pragma unroll
    for (int j = lane; j < DD / 4; j += 32) {   // 6 float4 per lane
        const float4 hv = h[j];
        const float4 wv = w[j];
        s = fmaf(hv.x, wv.x, s);
        s = fmaf(hv.y, wv.y, s);
        s = fmaf(hv.z, wv.z, s);
        s = fmaf(hv.w, wv.w, s);
    }
    #pragma unroll
    for (int o = 16; o > 0; o >>= 1) s += __shfl_down_sync(0xffffffffu, s, o);
    if (lane == 0) g_ctx[b][d] = s + bv[d];
}

// ---------------------------------------------------------------------------
// 5) out[b,l,:] = ctx[b,:]   — 50 MB streaming write, float4 stores.
//    grid (LL/16, BB), 192 threads, 16 rows per block.
// ---------------------------------------------------------------------------
__global__ void bcast_kernel(float* __restrict__ out) {
    const int b = blockIdx.y;
    const int t = threadIdx.x;                  // 192 = DD/4
    const float4 v = __ldg(&((const float4*)g_ctx[b])[t]);

    float4* __restrict__ dst =
        (float4*)(out + ((size_t)b * LL + (size_t)blockIdx.x * 16) * DD);
    #pragma unroll
    for (int r = 0; r < 16; r++)
        dst[(size_t)r * (DD / 4) + t] = v;
}

// ---------------------------------------------------------------------------
// Inputs (metadata order): hidden_states, attention_mask, Wq, bq, Wk, bk, Wv, bv
// Q/K are dead math — never touched.
// ---------------------------------------------------------------------------
extern "C" void kernel_launch(void* const* d_in, const int* in_sizes, int n_in,
                              void* d_out, int out_size) {
    const float* hs   = (const float*)d_in[0];
    const float* mask = (const float*)d_in[1];
    const float* Wv   = (const float*)d_in[6];
    const float* bv   = (const float*)d_in[7];
    float* out = (float*)d_out;

    probs_kernel<<<BB, 1024>>>(mask);
    wsum_kernel<<<dim3(CHUNKS, BB), DD / 4>>>(hs);
    reduce_kernel<<<(BB * DD + 255) / 256, 256>>>();
    gemv_kernel<<<(BB * DD) / 8, 256>>>(Wv, bv);   // 8 warps/block, warp per output
    bcast_kernel<<<dim3(LL / 16, BB), DD / 4>>>(out);
}

// round 2
// speedup vs baseline: 1.1197x; 1.1197x over previous
#include <cuda_runtime.h>

// Problem constants
#define BB 4
#define LL 4096
#define DD 768
#define CHUNKS 128
#define ROWS 32            // LL / CHUNKS
#define PF 48              // Wv L2-prefetch blocks riding on wsum launch
#define KSPL 4             // gemv split-K factor
#define KS (DD / KSPL)     // 192 k-elements per slice

// Scratch (device globals — no allocations allowed)
__device__ float g_partial[CHUNKS][BB][DD];   // per-chunk exp-weighted sums
__device__ float g_wsum[CHUNKS][BB];          // per-chunk exp-weight sums
__device__ float g_hbar[BB][DD];              // normalized probs·hs
__device__ float g_ctxp[KSPL][BB][DD];        // split-K gemv partials
__device__ float g_sink;                      // DCE defeat for prefetch

// ---------------------------------------------------------------------------
// 1) wsum: partial[c][b][:] = Σ_{l in chunk} exp(mask[b,l]) * hs[b,l,:]
//    plus per-chunk weight sums. Extra blocks (x >= CHUNKS) prefetch Wv
//    into L2 so the later gemv hits L2 instead of cold DRAM.
//    Softmax normalization is deferred: probs = exp / Σexp and mask ≤ 0,
//    so exp() needs no max-subtraction and division happens in reduce.
// ---------------------------------------------------------------------------
__global__ void __launch_bounds__(192) wsum_kernel(const float* __restrict__ hs,
                                                   const float* __restrict__ mask,
                                                   const float* __restrict__ Wv) {
    const int t = threadIdx.x;                 // 192 = DD/4

    if (blockIdx.x >= CHUNKS) {                // Wv prefetch blocks
        if (blockIdx.y != 0) return;
        const int pb = blockIdx.x - CHUNKS;    // 0..PF-1
        const float4* __restrict__ w4 = (const float4*)Wv;
        float acc = 0.0f;
        #pragma unroll
        for (int i = 0; i < 16; i++) {         // PF*192*16 = 147456 = DD*DD/4
            const float4 v = __ldg(&w4[(size_t)pb * (16 * 192) + i * 192 + t]);
            acc += v.x + v.y + v.z + v.w;
        }
        if (acc == 1.23456789e30f) g_sink = acc;   // never true; defeats DCE
        return;
    }

    const int c = blockIdx.x;
    const int b = blockIdx.y;

    __shared__ float p[ROWS];
    if (t < ROWS) {                            // warp 0, all 32 lanes active
        float w = expf(__ldg(&mask[(size_t)b * LL + c * ROWS + t]));
        p[t] = w;
        #pragma unroll
        for (int o = 16; o > 0; o >>= 1) w += __shfl_down_sync(0xffffffffu, w, o);
        if (t == 0) g_wsum[c][b] = w;
    }
    __syncthreads();

    const float4* __restrict__ src =
        (const float4*)(hs + ((size_t)b * LL + (size_t)c * ROWS) * DD);

    float4 acc = make_float4(0.f, 0.f, 0.f, 0.f);
    #pragma unroll 8
    for (int r = 0; r < ROWS; r++) {
        const float4 x = src[(size_t)r * (DD / 4) + t];
        const float pr = p[r];
        acc.x = fmaf(pr, x.x, acc.x);
        acc.y = fmaf(pr, x.y, acc.y);
        acc.z = fmaf(pr, x.z, acc.z);
        acc.w = fmaf(pr, x.w, acc.w);
    }
    ((float4*)g_partial[c][b])[t] = acc;
}

// ---------------------------------------------------------------------------
// 2) reduce: hbar[b][k] = (Σ_c partial[c][b][k]) / (Σ_c wsum[c][b])
//    grid 12 x 256 — one thread per output, per-block redundant invw compute.
// ---------------------------------------------------------------------------
__global__ void __launch_bounds__(256) reduce_kernel() {
    __shared__ float invw[BB];
    const int t = threadIdx.x;
    const int wid = t >> 5, lane = t & 31;

    if (wid < BB) {                            // warps 0..3: one batch each
        float s = 0.0f;
        #pragma unroll
        for (int i = 0; i < 4; i++) s += g_wsum[lane + 32 * i][wid];
        #pragma unroll
        for (int o = 16; o > 0; o >>= 1) s += __shfl_down_sync(0xffffffffu, s, o);
        if (lane == 0) invw[wid] = 1.0f / s;
    }
    __syncthreads();

    const int o = blockIdx.x * 256 + t;        // 0..3071
    const int b = o / DD, k = o % DD;
    float s = 0.0f;
    #pragma unroll 8
    for (int c = 0; c < CHUNKS; c++) s += g_partial[c][b][k];
    g_hbar[b][k] = s * invw[b];
}

// ---------------------------------------------------------------------------
// 3) gemv split-K: ctxp[s][b][d] = Σ_{k in slice s} hbar[b][k] * Wv[d][k]
//    12288 warps (4x the outputs) — 4x in-flight loads vs R1; Wv is L2-warm.
// ---------------------------------------------------------------------------
__global__ void __launch_bounds__(256) gemv_kernel(const float* __restrict__ Wv) {
    const int w    = (blockIdx.x * 256 + threadIdx.x) >> 5;  // 0..12287
    const int lane = threadIdx.x & 31;
    const int s    = w / (BB * DD);
    const int rem  = w % (BB * DD);
    const int b    = rem / DD, d = rem % DD;

    const float2* __restrict__ h2 = (const float2*)(g_hbar[b]) + s * (KS / 2);
    const float2* __restrict__ w2 = (const float2*)(Wv + (size_t)d * DD) + s * (KS / 2);

    float acc = 0.0f;
    #pragma unroll
    for (int i = 0; i < 3; i++) {              // KS/2 = 96 float2 over 32 lanes
        const float2 hv = h2[lane + 32 * i];
        const float2 wv = __ldg(&w2[lane + 32 * i]);
        acc = fmaf(hv.x, wv.x, fmaf(hv.y, wv.y, acc));
    }
    #pragma unroll
    for (int o = 16; o > 0; o >>= 1) acc += __shfl_down_sync(0xffffffffu, acc, o);
    if (lane == 0) g_ctxp[s][b][d] = acc;
}

// ---------------------------------------------------------------------------
// 4) bcast: out[b,l,:] = Σ_s ctxp[s][b][:] + bv  (combine folded in; 50MB write)
// ---------------------------------------------------------------------------
__global__ void __launch_bounds__(192) bcast_kernel(float* __restrict__ out,
                                                    const float* __restrict__ bv) {
    const int b = blockIdx.y;
    const int t = threadIdx.x;                 // 192 = DD/4

    float4 v = __ldg(&((const float4*)bv)[t]);
    #pragma unroll
    for (int s = 0; s < KSPL; s++) {
        const float4 p = ((const float4*)g_ctxp[s][b])[t];
        v.x += p.x; v.y += p.y; v.z += p.z; v.w += p.w;
    }

    float4* __restrict__ dst =
        (float4*)(out + ((size_t)b * LL + (size_t)blockIdx.x * 16) * DD);
    #pragma unroll
    for (int r = 0; r < 16; r++)
        dst[(size_t)r * (DD / 4) + t] = v;
}

// ---------------------------------------------------------------------------
// Inputs: hidden_states, attention_mask, Wq, bq, Wk, bk, Wv, bv (Q/K dead)
// ---------------------------------------------------------------------------
extern "C" void kernel_launch(void* const* d_in, const int* in_sizes, int n_in,
                              void* d_out, int out_size) {
    const float* hs   = (const float*)d_in[0];
    const float* mask = (const float*)d_in[1];
    const float* Wv   = (const float*)d_in[6];
    const float* bv   = (const float*)d_in[7];
    float* out = (float*)d_out;

    wsum_kernel  <<<dim3(CHUNKS + PF, BB), 192>>>(hs, mask, Wv);
    reduce_kernel<<<(BB * DD) / 256, 256>>>();
    gemv_kernel  <<<(KSPL * BB * DD * 32) / 256, 256>>>(Wv);
    bcast_kernel <<<dim3(LL / 16, BB), 192>>>(out, bv);
}

// round 3
// speedup vs baseline: 1.2320x; 1.1003x over previous
#include <cuda_runtime.h>
#include <cstdint>

// Problem constants
#define BB 4
#define LL 4096
#define DD 768
#define CHUNKS 256
#define ROWS 16            // LL / CHUNKS
#define PF 48              // Wv L2-prefetch blocks riding on wsum launch
#define KSPL 4             // gemv split-K factor
#define KS (DD / KSPL)     // 192 k-elements per slice
#define TROWS 16           // rows per smem tile in bcast (48KB)
#define SPAN 32            // output rows per bcast block

// Scratch (device globals — no allocations allowed)
__device__ float g_partial[CHUNKS][BB][DD];   // per-chunk exp-weighted sums
__device__ float g_wsum[CHUNKS][BB];          // per-chunk exp-weight sums
__device__ float g_hbar[BB][DD];              // normalized probs·hs
__device__ float g_ctx[BB][DD];               // final context row (bias folded)
__device__ float g_sink;                      // DCE defeat for prefetch

// ---------------------------------------------------------------------------
// 1) wsum: partial[c][b][:] = Σ_{l in chunk} exp(mask[b,l]) * hs[b,l,:]
//    (softmax normalization deferred to reduce; mask ≤ 0 so exp is safe).
//    Blocks x >= CHUNKS prefetch Wv into L2 for the later gemv.
// ---------------------------------------------------------------------------
__global__ void __launch_bounds__(192) wsum_kernel(const float* __restrict__ hs,
                                                   const float* __restrict__ mask,
                                                   const float* __restrict__ Wv) {
    const int t = threadIdx.x;                 // 192 = DD/4

    if (blockIdx.x >= CHUNKS) {                // Wv prefetch blocks
        if (blockIdx.y != 0) return;
        const int pb = blockIdx.x - CHUNKS;    // 0..PF-1
        const float4* __restrict__ w4 = (const float4*)Wv;
        float acc = 0.0f;
        #pragma unroll
        for (int i = 0; i < 16; i++) {         // PF*192*16 = DD*DD/4
            const float4 v = __ldg(&w4[(size_t)pb * (16 * 192) + i * 192 + t]);
            acc += v.x + v.y + v.z + v.w;
        }
        if (acc == 1.23456789e30f) g_sink = acc;   // never true; defeats DCE
        return;
    }

    const int c = blockIdx.x;
    const int b = blockIdx.y;

    __shared__ float p[ROWS];
    if (t < ROWS) {                            // lanes 0..15 of warp 0
        float w = expf(__ldg(&mask[(size_t)b * LL + c * ROWS + t]));
        p[t] = w;
        #pragma unroll
        for (int o = 8; o > 0; o >>= 1) w += __shfl_down_sync(0x0000ffffu, w, o, 16);
        if (t == 0) g_wsum[c][b] = w;
    }
    __syncthreads();

    const float4* __restrict__ src =
        (const float4*)(hs + ((size_t)b * LL + (size_t)c * ROWS) * DD);

    float4 acc = make_float4(0.f, 0.f, 0.f, 0.f);
    #pragma unroll
    for (int r = 0; r < ROWS; r++) {
        const float4 x = src[(size_t)r * (DD / 4) + t];
        const float pr = p[r];
        acc.x = fmaf(pr, x.x, acc.x);
        acc.y = fmaf(pr, x.y, acc.y);
        acc.z = fmaf(pr, x.z, acc.z);
        acc.w = fmaf(pr, x.w, acc.w);
    }
    ((float4*)g_partial[c][b])[t] = acc;
}

// ---------------------------------------------------------------------------
// 2) reduce: hbar[b][k] = (Σ_c partial[c][b][k]) / (Σ_c wsum[c][b])
//    48 blocks; each output summed by 4 threads (64 chunks each) + smem fold.
// ---------------------------------------------------------------------------
__global__ void __launch_bounds__(256) reduce_kernel() {
    __shared__ float invw[BB];
    __shared__ float sm[256];
    const int t = threadIdx.x;
    const int wid = t >> 5, lane = t & 31;

    if (wid < BB) {                            // warps 0..3: one batch each
        float s = 0.0f;
        #pragma unroll
        for (int i = 0; i < CHUNKS / 32; i++) s += g_wsum[lane + 32 * i][wid];
        #pragma unroll
        for (int o = 16; o > 0; o >>= 1) s += __shfl_down_sync(0xffffffffu, s, o);
        if (lane == 0) invw[wid] = 1.0f / s;
    }
    __syncthreads();

    const int g  = t >> 6;                     // chunk group 0..3
    const int ol = t & 63;                     // local output 0..63
    {
        const int o = blockIdx.x * 64 + ol;    // 0..3071 (64 | 768, b uniform)
        const int b = o / DD, k = o % DD;
        float s = 0.0f;
        #pragma unroll 8
        for (int c = g * 64; c < (g + 1) * 64; c++) s += g_partial[c][b][k];
        sm[t] = s;
    }
    __syncthreads();
    if (t < 64) {
        const int o = blockIdx.x * 64 + t;
        const int b = o / DD, k = o % DD;
        g_hbar[b][k] = (sm[t] + sm[t + 64] + sm[t + 128] + sm[t + 192]) * invw[b];
    }
}

// ---------------------------------------------------------------------------
// 3) gemv: ctx[b][d] = hbar[b,:]·Wv[d,:] + bv[d]
//    8 warps/block = 2 outputs x 4 k-slices; slice combine in smem.
// ---------------------------------------------------------------------------
__global__ void __launch_bounds__(256) gemv_kernel(const float* __restrict__ Wv,
                                                   const float* __restrict__ bv) {
    __shared__ float part[8];
    const int w    = threadIdx.x >> 5;         // 0..7
    const int lane = threadIdx.x & 31;
    const int oidx = blockIdx.x * 2 + (w >> 2);  // 0..3071
    const int s    = w & 3;
    const int b    = oidx / DD, d = oidx % DD;

    const float2* __restrict__ h2 = (const float2*)(g_hbar[b]) + s * (KS / 2);
    const float2* __restrict__ w2 = (const float2*)(Wv + (size_t)d * DD) + s * (KS / 2);

    float acc = 0.0f;
    #pragma unroll
    for (int i = 0; i < 3; i++) {              // KS/2 = 96 float2 over 32 lanes
        const float2 hv = h2[lane + 32 * i];
        const float2 wv = __ldg(&w2[lane + 32 * i]);
        acc = fmaf(hv.x, wv.x, fmaf(hv.y, wv.y, acc));
    }
    #pragma unroll
    for (int o = 16; o > 0; o >>= 1) acc += __shfl_down_sync(0xffffffffu, acc, o);
    if (lane == 0) part[w] = acc;
    __syncthreads();
    if (threadIdx.x < 2) {
        const int o2 = blockIdx.x * 2 + threadIdx.x;
        const float r = part[threadIdx.x * 4] + part[threadIdx.x * 4 + 1] +
                        part[threadIdx.x * 4 + 2] + part[threadIdx.x * 4 + 3] +
                        __ldg(&bv[o2 % DD]);
        g_ctx[o2 / DD][o2 % DD] = r;
    }
}

// ---------------------------------------------------------------------------
// 4) bcast: out[b,l,:] = ctx[b,:] via TMA bulk stores.
//    Fill 48KB smem tile (16 identical rows), then 2 x cp.async.bulk of 48KB
//    — SMEM->L2 through the TMA engine, bypassing the LSU store path.
// ---------------------------------------------------------------------------
__global__ void __launch_bounds__(192) bcast_kernel(float* __restrict__ out) {
    __shared__ __align__(16) float4 tile[TROWS * 192];   // 48KB
    const int b = blockIdx.y;
    const int t = threadIdx.x;                 // 192 = DD/4

    const float4 v = __ldg(&((const float4*)g_ctx[b])[t]);
    #pragma unroll
    for (int r = 0; r < TROWS; r++) tile[r * 192 + t] = v;
    __syncthreads();

    if (t == 0) {
        asm volatile("fence.proxy.async.shared::cta;" ::: "memory");
        const uint32_t saddr = (uint32_t)__cvta_generic_to_shared(tile);
        float* dst = out + ((size_t)b * LL + (size_t)blockIdx.x * SPAN) * DD;
        #pragma unroll
        for (int i = 0; i < SPAN / TROWS; i++) {
            asm volatile(
                "cp.async.bulk.global.shared::cta.bulk_group [%0], [%1], %2;"
                :: "l"(dst + (size_t)i * TROWS * DD), "r"(saddr),
                   "r"((int)(TROWS * DD * 4))
                : "memory");
        }
        asm volatile("cp.async.bulk.commit_group;" ::: "memory");
        asm volatile("cp.async.bulk.wait_group 0;" ::: "memory");
    }
    __syncthreads();
}

// ---------------------------------------------------------------------------
// Inputs: hidden_states, attention_mask, Wq, bq, Wk, bk, Wv, bv (Q/K dead)
// ---------------------------------------------------------------------------
extern "C" void kernel_launch(void* const* d_in, const int* in_sizes, int n_in,
                              void* d_out, int out_size) {
    const float* hs   = (const float*)d_in[0];
    const float* mask = (const float*)d_in[1];
    const float* Wv   = (const float*)d_in[6];
    const float* bv   = (const float*)d_in[7];
    float* out = (float*)d_out;

    wsum_kernel  <<<dim3(CHUNKS + PF, BB), 192>>>(hs, mask, Wv);
    reduce_kernel<<<48, 256>>>();
    gemv_kernel  <<<(BB * DD) / 2, 256>>>(Wv, bv);
    bcast_kernel <<<dim3(LL / SPAN, BB), 192>>>(out);
}

// round 4
// speedup vs baseline: 1.3556x; 1.1003x over previous
#include <cuda_runtime.h>
#include <cstdint>

// Problem constants
#define BB 4
#define LL 4096
#define DD 768
#define CHUNKS 128
#define ROWS 32            // LL / CHUNKS
#define PF 48              // Wv L2-prefetch blocks riding on wsum launch
#define KSPL 4             // gemv split-K factor
#define KS (DD / KSPL)     // 192 k-elements per slice
#define TROWS 8            // rows per smem tile in bcast (24KB -> high occ)
#define SPAN 32            // output rows per bcast block (4 bulk copies)

// Scratch (device globals — no allocations allowed)
__device__ float g_partial[CHUNKS][BB][DD];   // per-chunk exp-weighted sums
__device__ float g_wsum[CHUNKS][BB];          // per-chunk exp-weight sums
__device__ float g_hbar[BB][DD];              // normalized probs·hs
__device__ float g_ctx[BB][DD];               // final context row (bias folded)
__device__ float g_sink;                      // DCE defeat for prefetch

// ---------------------------------------------------------------------------
// 1) wsum: partial[c][b][:] = Σ_{l in chunk, w(l)!=0} exp(mask[b,l])*hs[b,l,:]
//    mask is {0, -1e9} so weights are exactly {1, 0}: zero-weight rows are
//    SKIPPED (block-uniform branch) — ~15% less read traffic, bit-identical.
//    Blocks x >= CHUNKS prefetch Wv into L2 for the later gemv.
// ---------------------------------------------------------------------------
__global__ void __launch_bounds__(192) wsum_kernel(const float* __restrict__ hs,
                                                   const float* __restrict__ mask,
                                                   const float* __restrict__ Wv) {
    const int t = threadIdx.x;                 // 192 = DD/4

    if (blockIdx.x >= CHUNKS) {                // Wv prefetch blocks
        if (blockIdx.y != 0) return;
        const int pb = blockIdx.x - CHUNKS;    // 0..PF-1
        const float4* __restrict__ w4 = (const float4*)Wv;
        float acc = 0.0f;
        #pragma unroll
        for (int i = 0; i < 16; i++) {         // PF*192*16 = DD*DD/4
            const float4 v = __ldg(&w4[(size_t)pb * (16 * 192) + i * 192 + t]);
            acc += v.x + v.y + v.z + v.w;
        }
        if (acc == 1.23456789e30f) g_sink = acc;   // never true; defeats DCE
        return;
    }

    const int c = blockIdx.x;
    const int b = blockIdx.y;

    __shared__ float p[ROWS];
    if (t < ROWS) {                            // warp 0
        float w = expf(__ldg(&mask[(size_t)b * LL + c * ROWS + t]));
        p[t] = w;
        #pragma unroll
        for (int o = 16; o > 0; o >>= 1) w += __shfl_down_sync(0xffffffffu, w, o);
        if (t == 0) g_wsum[c][b] = w;
    }
    __syncthreads();

    const float4* __restrict__ src =
        (const float4*)(hs + ((size_t)b * LL + (size_t)c * ROWS) * DD);

    float4 acc = make_float4(0.f, 0.f, 0.f, 0.f);
    #pragma unroll 8
    for (int r = 0; r < ROWS; r++) {
        const float pr = p[r];
        if (pr != 0.0f) {                      // uniform branch: skip dead rows
            const float4 x = src[(size_t)r * (DD / 4) + t];
            acc.x = fmaf(pr, x.x, acc.x);
            acc.y = fmaf(pr, x.y, acc.y);
            acc.z = fmaf(pr, x.z, acc.z);
            acc.w = fmaf(pr, x.w, acc.w);
        }
    }
    ((float4*)g_partial[c][b])[t] = acc;
}

// ---------------------------------------------------------------------------
// 2) reduce: hbar[b][k] = (Σ_c partial[c][b][k]) / (Σ_c wsum[c][b])
//    48 blocks; each output summed by 4 threads (32 chunks each) + smem fold.
// ---------------------------------------------------------------------------
__global__ void __launch_bounds__(256) reduce_kernel() {
    __shared__ float invw[BB];
    __shared__ float sm[256];
    const int t = threadIdx.x;
    const int wid = t >> 5, lane = t & 31;

    if (wid < BB) {                            // warps 0..3: one batch each
        float s = 0.0f;
        #pragma unroll
        for (int i = 0; i < CHUNKS / 32; i++) s += g_wsum[lane + 32 * i][wid];
        #pragma unroll
        for (int o = 16; o > 0; o >>= 1) s += __shfl_down_sync(0xffffffffu, s, o);
        if (lane == 0) invw[wid] = 1.0f / s;
    }
    __syncthreads();

    const int g  = t >> 6;                     // chunk group 0..3 (32 chunks each)
    const int ol = t & 63;                     // local output 0..63
    {
        const int o = blockIdx.x * 64 + ol;    // 0..3071
        const int b = o / DD, k = o % DD;
        float s = 0.0f;
        #pragma unroll 8
        for (int c = g * 32; c < (g + 1) * 32; c++) s += g_partial[c][b][k];
        sm[t] = s;
    }
    __syncthreads();
    if (t < 64) {
        const int o = blockIdx.x * 64 + t;
        const int b = o / DD, k = o % DD;
        g_hbar[b][k] = (sm[t] + sm[t + 64] + sm[t + 128] + sm[t + 192]) * invw[b];
    }
}

// ---------------------------------------------------------------------------
// 3) gemv: ctx[b][d] = hbar[b,:]·Wv[d,:] + bv[d]
//    8 warps/block = 2 outputs x 4 k-slices; slice combine in smem.
// ---------------------------------------------------------------------------
__global__ void __launch_bounds__(256) gemv_kernel(const float* __restrict__ Wv,
                                                   const float* __restrict__ bv) {
    __shared__ float part[8];
    const int w    = threadIdx.x >> 5;         // 0..7
    const int lane = threadIdx.x & 31;
    const int oidx = blockIdx.x * 2 + (w >> 2);  // 0..3071
    const int s    = w & 3;
    const int b    = oidx / DD, d = oidx % DD;

    const float2* __restrict__ h2 = (const float2*)(g_hbar[b]) + s * (KS / 2);
    const float2* __restrict__ w2 = (const float2*)(Wv + (size_t)d * DD) + s * (KS / 2);

    float acc = 0.0f;
    #pragma unroll
    for (int i = 0; i < 3; i++) {              // KS/2 = 96 float2 over 32 lanes
        const float2 hv = h2[lane + 32 * i];
        const float2 wv = __ldg(&w2[lane + 32 * i]);
        acc = fmaf(hv.x, wv.x, fmaf(hv.y, wv.y, acc));
    }
    #pragma unroll
    for (int o = 16; o > 0; o >>= 1) acc += __shfl_down_sync(0xffffffffu, acc, o);
    if (lane == 0) part[w] = acc;
    __syncthreads();
    if (threadIdx.x < 2) {
        const int o2 = blockIdx.x * 2 + threadIdx.x;
        const float r = part[threadIdx.x * 4] + part[threadIdx.x * 4 + 1] +
                        part[threadIdx.x * 4 + 2] + part[threadIdx.x * 4 + 3] +
                        __ldg(&bv[o2 % DD]);
        g_ctx[o2 / DD][o2 % DD] = r;
    }
}

// ---------------------------------------------------------------------------
// 4) bcast: out[b,l,:] = ctx[b,:] via TMA bulk stores.
//    Small 24KB tile (8 rows) -> ~9 blocks/SM occupancy; 4 async bulk
//    copies per block, commit once, single wait at the end.
// ---------------------------------------------------------------------------
__global__ void __launch_bounds__(192) bcast_kernel(float* __restrict__ out) {
    __shared__ __align__(16) float4 tile[TROWS * 192];   // 24KB
    const int b = blockIdx.y;
    const int t = threadIdx.x;                 // 192 = DD/4

    const float4 v = __ldg(&((const float4*)g_ctx[b])[t]);
    #pragma unroll
    for (int r = 0; r < TROWS; r++) tile[r * 192 + t] = v;
    __syncthreads();

    if (t == 0) {
        asm volatile("fence.proxy.async.shared::cta;" ::: "memory");
        const uint32_t saddr = (uint32_t)__cvta_generic_to_shared(tile);
        float* dst = out + ((size_t)b * LL + (size_t)blockIdx.x * SPAN) * DD;
        #pragma unroll
        for (int i = 0; i < SPAN / TROWS; i++) {
            asm volatile(
                "cp.async.bulk.global.shared::cta.bulk_group [%0], [%1], %2;"
                :: "l"(dst + (size_t)i * TROWS * DD), "r"(saddr),
                   "r"((int)(TROWS * DD * 4))
                : "memory");
        }
        asm volatile("cp.async.bulk.commit_group;" ::: "memory");
        asm volatile("cp.async.bulk.wait_group 0;" ::: "memory");
    }
    __syncthreads();
}

// ---------------------------------------------------------------------------
// Inputs: hidden_states, attention_mask, Wq, bq, Wk, bk, Wv, bv (Q/K dead)
// ---------------------------------------------------------------------------
extern "C" void kernel_launch(void* const* d_in, const int* in_sizes, int n_in,
                              void* d_out, int out_size) {
    const float* hs   = (const float*)d_in[0];
    const float* mask = (const float*)d_in[1];
    const float* Wv   = (const float*)d_in[6];
    const float* bv   = (const float*)d_in[7];
    float* out = (float*)d_out;

    wsum_kernel  <<<dim3(CHUNKS + PF, BB), 192>>>(hs, mask, Wv);
    reduce_kernel<<<48, 256>>>();
    gemv_kernel  <<<(BB * DD) / 2, 256>>>(Wv, bv);
    bcast_kernel <<<dim3(LL / SPAN, BB), 192>>>(out);
}

// round 5
// speedup vs baseline: 1.4442x; 1.0653x over previous
#include <cuda_runtime.h>
#include <cstdint>

// Problem constants
#define BB 4
#define LL 4096
#define DD 768
#define CHUNKS 256
#define ROWS 16            // LL / CHUNKS
#define PF 48              // Wv L2-prefetch blocks riding on wsum launch
#define KSPL 4             // gemv split-K factor
#define KS (DD / KSPL)     // 192 k-elements per slice
#define TROWS 8            // rows per smem tile in bcast (24KB)
#define SPAN 16            // output rows per bcast block (2 bulk copies)

// Scratch (device globals — no allocations allowed)
__device__ float g_partial[CHUNKS][BB][DD];   // per-chunk exp-weighted sums
__device__ float g_wsum[CHUNKS][BB];          // per-chunk exp-weight sums
__device__ float g_hbar[BB][DD];              // normalized probs·hs
__device__ float g_ctx[BB][DD];               // final context row (bias folded)
__device__ float g_sink;                      // DCE defeat for prefetch

// ---------------------------------------------------------------------------
// 1) wsum: partial[c][b][:] = Σ_{l in chunk, w(l)!=0} exp(mask[b,l])*hs[b,l,:]
//    mask is {0, -1e9} so weights are exactly {1, 0}: zero-weight rows are
//    SKIPPED (block-uniform branch). Blocks x >= CHUNKS prefetch Wv into L2.
// ---------------------------------------------------------------------------
__global__ void __launch_bounds__(192) wsum_kernel(const float* __restrict__ hs,
                                                   const float* __restrict__ mask,
                                                   const float* __restrict__ Wv) {
    const int t = threadIdx.x;                 // 192 = DD/4

    if (blockIdx.x >= CHUNKS) {                // Wv prefetch blocks
        if (blockIdx.y != 0) return;
        const int pb = blockIdx.x - CHUNKS;    // 0..PF-1
        const float4* __restrict__ w4 = (const float4*)Wv;
        float acc = 0.0f;
        #pragma unroll
        for (int i = 0; i < 16; i++) {         // PF*192*16 = DD*DD/4
            const float4 v = __ldg(&w4[(size_t)pb * (16 * 192) + i * 192 + t]);
            acc += v.x + v.y + v.z + v.w;
        }
        if (acc == 1.23456789e30f) g_sink = acc;   // never true; defeats DCE
        return;
    }

    const int c = blockIdx.x;
    const int b = blockIdx.y;

    __shared__ float p[ROWS];
    if (t < ROWS) {                            // lanes 0..15 of warp 0
        float w = expf(__ldg(&mask[(size_t)b * LL + c * ROWS + t]));
        p[t] = w;
        #pragma unroll
        for (int o = 8; o > 0; o >>= 1) w += __shfl_down_sync(0x0000ffffu, w, o, 16);
        if (t == 0) g_wsum[c][b] = w;
    }
    __syncthreads();

    const float4* __restrict__ src =
        (const float4*)(hs + ((size_t)b * LL + (size_t)c * ROWS) * DD);

    float4 acc = make_float4(0.f, 0.f, 0.f, 0.f);
    #pragma unroll
    for (int r = 0; r < ROWS; r++) {
        const float pr = p[r];
        if (pr != 0.0f) {                      // uniform branch: skip dead rows
            const float4 x = src[(size_t)r * (DD / 4) + t];
            acc.x = fmaf(pr, x.x, acc.x);
            acc.y = fmaf(pr, x.y, acc.y);
            acc.z = fmaf(pr, x.z, acc.z);
            acc.w = fmaf(pr, x.w, acc.w);
        }
    }
    ((float4*)g_partial[c][b])[t] = acc;
}

// ---------------------------------------------------------------------------
// 2) reduce: hbar[b][k] = (Σ_c partial[c][b][k]) / (Σ_c wsum[c][b])
//    48 blocks; each output summed by 4 threads (64 chunks each) + smem fold.
// ---------------------------------------------------------------------------
__global__ void __launch_bounds__(256) reduce_kernel() {
#if __CUDA_ARCH__ >= 900
    cudaGridDependencySynchronize();           // PDL: wait for wsum's writes
#endif
    __shared__ float invw[BB];
    __shared__ float sm[256];
    const int t = threadIdx.x;
    const int wid = t >> 5, lane = t & 31;

    if (wid < BB) {                            // warps 0..3: one batch each
        float s = 0.0f;
        #pragma unroll
        for (int i = 0; i < CHUNKS / 32; i++) s += g_wsum[lane + 32 * i][wid];
        #pragma unroll
        for (int o = 16; o > 0; o >>= 1) s += __shfl_down_sync(0xffffffffu, s, o);
        if (lane == 0) invw[wid] = 1.0f / s;
    }
    __syncthreads();

    const int g  = t >> 6;                     // chunk group 0..3 (64 chunks each)
    const int ol = t & 63;                     // local output 0..63
    {
        const int o = blockIdx.x * 64 + ol;    // 0..3071
        const int b = o / DD, k = o % DD;
        float s = 0.0f;
        #pragma unroll 8
        for (int c = g * 64; c < (g + 1) * 64; c++) s += g_partial[c][b][k];
        sm[t] = s;
    }
    __syncthreads();
    if (t < 64) {
        const int o = blockIdx.x * 64 + t;
        const int b = o / DD, k = o % DD;
        g_hbar[b][k] = (sm[t] + sm[t + 64] + sm[t + 128] + sm[t + 192]) * invw[b];
    }
}

// ---------------------------------------------------------------------------
// 3) gemv: ctx[b][d] = hbar[b,:]·Wv[d,:] + bv[d]
//    8 warps/block = 2 outputs x 4 k-slices; slice combine in smem.
// ---------------------------------------------------------------------------
__global__ void __launch_bounds__(256) gemv_kernel(const float* __restrict__ Wv,
                                                   const float* __restrict__ bv) {
#if __CUDA_ARCH__ >= 900
    cudaGridDependencySynchronize();           // PDL: wait for reduce's writes
#endif
    __shared__ float part[8];
    const int w    = threadIdx.x >> 5;         // 0..7
    const int lane = threadIdx.x & 31;
    const int oidx = blockIdx.x * 2 + (w >> 2);  // 0..3071
    const int s    = w & 3;
    const int b    = oidx / DD, d = oidx % DD;

    const float2* __restrict__ h2 = (const float2*)(g_hbar[b]) + s * (KS / 2);
    const float2* __restrict__ w2 = (const float2*)(Wv + (size_t)d * DD) + s * (KS / 2);

    float acc = 0.0f;
    #pragma unroll
    for (int i = 0; i < 3; i++) {              // KS/2 = 96 float2 over 32 lanes
        const float2 hv = h2[lane + 32 * i];
        const float2 wv = __ldg(&w2[lane + 32 * i]);
        acc = fmaf(hv.x, wv.x, fmaf(hv.y, wv.y, acc));
    }
    #pragma unroll
    for (int o = 16; o > 0; o >>= 1) acc += __shfl_down_sync(0xffffffffu, acc, o);
    if (lane == 0) part[w] = acc;
    __syncthreads();
    if (threadIdx.x < 2) {
        const int o2 = blockIdx.x * 2 + threadIdx.x;
        const float r = part[threadIdx.x * 4] + part[threadIdx.x * 4 + 1] +
                        part[threadIdx.x * 4 + 2] + part[threadIdx.x * 4 + 3] +
                        __ldg(&bv[o2 % DD]);
        g_ctx[o2 / DD][o2 % DD] = r;
    }
}

// ---------------------------------------------------------------------------
// 4) bcast: out[b,l,:] = ctx[b,:] via TMA bulk stores.
//    L2 write wall ~4.2TB/s is the floor; SPAN=16 (1024 blocks) smooths the
//    last wave across 148 SMs.
// ---------------------------------------------------------------------------
__global__ void __launch_bounds__(192) bcast_kernel(float* __restrict__ out) {
#if __CUDA_ARCH__ >= 900
    cudaGridDependencySynchronize();           // PDL: wait for gemv's writes
#endif
    __shared__ __align__(16) float4 tile[TROWS * 192];   // 24KB
    const int b = blockIdx.y;
    const int t = threadIdx.x;                 // 192 = DD/4

    const float4 v = __ldg(&((const float4*)g_ctx[b])[t]);
    #pragma unroll
    for (int r = 0; r < TROWS; r++) tile[r * 192 + t] = v;
    __syncthreads();

    if (t == 0) {
        asm volatile("fence.proxy.async.shared::cta;" ::: "memory");
        const uint32_t saddr = (uint32_t)__cvta_generic_to_shared(tile);
        float* dst = out + ((size_t)b * LL + (size_t)blockIdx.x * SPAN) * DD;
        #pragma unroll
        for (int i = 0; i < SPAN / TROWS; i++) {
            asm volatile(
                "cp.async.bulk.global.shared::cta.bulk_group [%0], [%1], %2;"
                :: "l"(dst + (size_t)i * TROWS * DD), "r"(saddr),
                   "r"((int)(TROWS * DD * 4))
                : "memory");
        }
        asm volatile("cp.async.bulk.commit_group;" ::: "memory");
        asm volatile("cp.async.bulk.wait_group 0;" ::: "memory");
    }
    __syncthreads();
}

// ---------------------------------------------------------------------------
// Launch helpers — PDL-attributed launches for the dependent kernels.
// ---------------------------------------------------------------------------
template <typename K, typename... Args>
static inline void launch_pdl(K kern, dim3 grid, dim3 block, Args... args) {
    cudaLaunchConfig_t cfg = {};
    cfg.gridDim = grid;
    cfg.blockDim = block;
    cudaLaunchAttribute attr[1];
    attr[0].id = cudaLaunchAttributeProgrammaticStreamSerialization;
    attr[0].val.programmaticStreamSerializationAllowed = 1;
    cfg.attrs = attr;
    cfg.numAttrs = 1;
    cudaLaunchKernelEx(&cfg, kern, args...);
}

// ---------------------------------------------------------------------------
// Inputs: hidden_states, attention_mask, Wq, bq, Wk, bk, Wv, bv (Q/K dead)
// ---------------------------------------------------------------------------
extern "C" void kernel_launch(void* const* d_in, const int* in_sizes, int n_in,
                              void* d_out, int out_size) {
    const float* hs   = (const float*)d_in[0];
    const float* mask = (const float*)d_in[1];
    const float* Wv   = (const float*)d_in[6];
    const float* bv   = (const float*)d_in[7];
    float* out = (float*)d_out;

    wsum_kernel<<<dim3(CHUNKS + PF, BB), 192>>>(hs, mask, Wv);
    launch_pdl(reduce_kernel, dim3(48), dim3(256));
    launch_pdl(gemv_kernel, dim3((BB * DD) / 2), dim3(256), Wv, bv);
    launch_pdl(bcast_kernel, dim3(LL / SPAN, BB), dim3(192), out);
}